// round 9
// baseline (speedup 1.0000x reference)
#include <cuda_runtime.h>
#include <cstdint>
#include <math.h>

// ---------------------------------------------------------------------------
// DBASolver: B=16, N=131072, C=2, P=6.  Single persistent kernel.
//   phase 1: double-buffered cp.async stages ALL per-node inputs (72B/node)
//            into smem; compute is pure LDS+FMA; SoA scratch + 27-scalar
//            per-(block,batch) partials. MLP lives in the async queue, not
//            registers -> latency covered even at 24 warps/SM.
//   phase 2: last block reduces partials + 16x damped 6x6 solve -> pose.
//   phase 3: blocks spin on epoch, then depth on their own (b, range)
//            (scratch L2-warm; inputs marked L2::evict_first to protect it).
// Grid (27,16)=432 blocks, __launch_bounds__(256,3): co-residency guaranteed.
// ---------------------------------------------------------------------------

#define MAXB  16
#define TPB   256
#define RBLK  27

// SoA per-node scratch: s0 = {hpd0..3}, s1 = {hpd4, hpd5, g_d, inv}
__device__ float4   g_s0[(size_t)MAXB * 131072];
__device__ float4   g_s1[(size_t)MAXB * 131072];
__device__ float    g_partial[(size_t)MAXB * RBLK * 27];
__device__ float    g_pose[MAXB * 6];
__device__ int      g_nanflag;
__device__ unsigned g_done;    // wraps to 0 each launch via atomicInc(total-1)
__device__ unsigned g_epoch;   // monotonically increasing across replays

struct SmemStage {
    float4 jp[3 * TPB];   // linear chunk layout: element k = Jp4[g0*3 + k]
    float2 rv[TPB];
    float2 wv[TPB];
    float2 jd[TPB];
};   // 18432 B

__device__ __forceinline__ void cp16(void* sdst, const void* gsrc,
                                     unsigned long long pol) {
    unsigned int s = (unsigned int)__cvta_generic_to_shared(sdst);
    asm volatile("cp.async.cg.shared.global.L2::cache_hint [%0], [%1], 16, %2;"
                 :: "r"(s), "l"(gsrc), "l"(pol) : "memory");
}
__device__ __forceinline__ void cp8(void* sdst, const void* gsrc,
                                    unsigned long long pol) {
    unsigned int s = (unsigned int)__cvta_generic_to_shared(sdst);
    asm volatile("cp.async.ca.shared.global.L2::cache_hint [%0], [%1], 8, %2;"
                 :: "r"(s), "l"(gsrc), "l"(pol) : "memory");
}

__device__ __forceinline__ void stage_tile(
    SmemStage* st, size_t g0, int m, unsigned long long pol,
    const float4* __restrict__ Jp4, const float2* __restrict__ r2,
    const float2* __restrict__ w2,  const float2* __restrict__ jd2)
{
    int tid = threadIdx.x;
    if (m == TPB) {
#pragma unroll
        for (int k = 0; k < 3; k++)
            cp16(&st->jp[k * TPB + tid], &Jp4[g0 * 3 + k * TPB + tid], pol);
        cp8(&st->rv[tid], &r2[g0 + tid], pol);
        cp8(&st->wv[tid], &w2[g0 + tid], pol);
        cp8(&st->jd[tid], &jd2[g0 + tid], pol);
    } else {
        for (int k = tid; k < 3 * m; k += TPB)
            cp16(&st->jp[k], &Jp4[g0 * 3 + k], pol);
        if (tid < m) {
            cp8(&st->rv[tid], &r2[g0 + tid], pol);
            cp8(&st->wv[tid], &w2[g0 + tid], pol);
            cp8(&st->jd[tid], &jd2[g0 + tid], pol);
        }
    }
}

// compute one node entirely from smem; store scratch; update accumulators
__device__ __forceinline__ void compute_node(
    const SmemStage* st, size_t gidx, float safe_l, float acc[27])
{
    int tid = threadIdx.x;
    float4 jpA = st->jp[tid * 3 + 0];   // 48B stride: conflict-free per phase
    float4 jpB = st->jp[tid * 3 + 1];
    float4 jpC = st->jp[tid * 3 + 2];
    float2 rv  = st->rv[tid];
    float2 wv  = st->wv[tid];
    float2 jdv = st->jd[tid];

    float conf = wv.x, nl = wv.y;
    float jp0[6] = { jpA.x, jpA.y, jpA.z, jpA.w, jpB.x, jpB.y };
    float jp1[6] = { jpB.z, jpB.w, jpC.x, jpC.y, jpC.z, jpC.w };

    float hpd[6];
#pragma unroll
    for (int p = 0; p < 6; p++)
        hpd[p] = conf * (jp0[p] * jdv.x + jp1[p] * jdv.y);

    float hdd = conf * (jdv.x * jdv.x + jdv.y * jdv.y);
    float gd  = conf * (jdv.x * rv.x  + jdv.y * rv.y);
    float inv = 1.0f / fmaxf(hdd + safe_l + nl + 1e-4f, 1e-4f);

    g_s0[gidx] = make_float4(hpd[0], hpd[1], hpd[2], hpd[3]);
    g_s1[gidx] = make_float4(hpd[4], hpd[5], gd, inv);

    int k = 0;
#pragma unroll
    for (int p = 0; p < 6; p++) {
        float cjp0p = conf * jp0[p];
        float cjp1p = conf * jp1[p];
        float tp    = inv  * hpd[p];
#pragma unroll
        for (int q = p; q < 6; q++) {
            float a = acc[k];
            a = fmaf(cjp0p, jp0[q], a);
            a = fmaf(cjp1p, jp1[q], a);
            a = fmaf(-tp,   hpd[q], a);
            acc[k++] = a;
        }
        float gp = cjp0p * rv.x + cjp1p * rv.y;
        acc[21 + p] += gp - tp * gd;
    }
}

__global__ void __launch_bounds__(TPB, 3)
dba_kernel(const float* __restrict__ r, const float* __restrict__ w,
           const float* __restrict__ Jp, const float* __restrict__ Jd,
           const float* __restrict__ lmbda, const int* __restrict__ iter_idx,
           float* __restrict__ out, int N, int B)
{
    __shared__ SmemStage sbuf[2];

    const int rblk = blockIdx.x;
    const int b    = blockIdx.y;
    const unsigned total_blocks = gridDim.x * gridDim.y;

    unsigned epoch0 = *(volatile unsigned*)&g_epoch;

    const size_t bn0 = (size_t)b * N;
    int npb   = (N + RBLK - 1) / RBLK;
    int start = rblk * npb;
    int end   = min(N, start + npb);
    int cnt   = end - start;

    float lm = lmbda[b];
    float safe_l = isnan(lm) ? 100.0f : lm;
    safe_l = fmaxf(safe_l, 0.001f);

    const float4* __restrict__ Jp4 = (const float4*)Jp;
    const float2* __restrict__ r2  = (const float2*)r;
    const float2* __restrict__ w2  = (const float2*)w;
    const float2* __restrict__ jd2 = (const float2*)Jd;

    unsigned long long pol;
    asm("createpolicy.fractional.L2::evict_first.b64 %0, 1.0;" : "=l"(pol));

    float acc[27];
#pragma unroll
    for (int i = 0; i < 27; i++) acc[i] = 0.0f;

    // ---- phase 1: double-buffered cp.async pipeline -----------------------
    int nTiles = (cnt + TPB - 1) / TPB;
    if (nTiles > 0) {
        stage_tile(&sbuf[0], bn0 + start, min(TPB, cnt), pol, Jp4, r2, w2, jd2);
    }
    asm volatile("cp.async.commit_group;" ::: "memory");

    for (int t = 0; t < nTiles; t++) {
        int nxt = start + (t + 1) * TPB;
        if (t + 1 < nTiles)
            stage_tile(&sbuf[(t + 1) & 1], bn0 + nxt, min(TPB, end - nxt),
                       pol, Jp4, r2, w2, jd2);
        asm volatile("cp.async.commit_group;" ::: "memory");
        asm volatile("cp.async.wait_group 1;" ::: "memory");
        __syncthreads();                      // tile t fully staged & visible

        int ts = start + t * TPB;
        int m  = min(TPB, end - ts);
        if (threadIdx.x < m)
            compute_node(&sbuf[t & 1], bn0 + ts + threadIdx.x, safe_l, acc);
        __syncthreads();                      // done reading buf before reuse
    }

    // warp reduce 27 values
#pragma unroll
    for (int i = 0; i < 27; i++) {
#pragma unroll
        for (int off = 16; off > 0; off >>= 1)
            acc[i] += __shfl_down_sync(0xFFFFFFFFu, acc[i], off);
    }

    __shared__ float sred[TPB / 32][27];
    int warp = threadIdx.x >> 5, lane = threadIdx.x & 31;
    if (lane == 0) {
#pragma unroll
        for (int i = 0; i < 27; i++) sred[warp][i] = acc[i];
    }
    __syncthreads();

    if (threadIdx.x < 27) {
        float s = 0.0f;
#pragma unroll
        for (int wd = 0; wd < TPB / 32; wd++) s += sred[wd][threadIdx.x];
        g_partial[((size_t)b * RBLK + rblk) * 27 + threadIdx.x] = s;
    }
    __syncthreads();

    // ---- phase 2: last block reduces + solves -----------------------------
    __shared__ bool s_last;
    if (threadIdx.x == 0) {
        __threadfence();
        unsigned old = atomicInc(&g_done, total_blocks - 1);
        s_last = (old == total_blocks - 1);
    }
    __syncthreads();

    if (s_last) {
        __shared__ float sH[MAXB][27];
        __shared__ int   s_nan;
        int t = threadIdx.x;
        if (t == 0) s_nan = 0;

        for (int slot = t; slot < B * 27; slot += TPB) {
            int bb = slot / 27, i = slot % 27;
            float s = 0.0f;
            for (int c = 0; c < RBLK; c++)
                s += g_partial[((size_t)bb * RBLK + c) * 27 + i];
            sH[bb][i] = s;
        }
        __syncthreads();

        int bb = t;
        if (bb < B) {
            float lm2 = lmbda[bb];
            float sl = isnan(lm2) ? 100.0f : lm2;
            sl = fmaxf(sl, 0.001f);

            float H[6][6], g[6];
            int k = 0;
            for (int p = 0; p < 6; p++)
                for (int q = p; q < 6; q++) { float v = sH[bb][k++]; H[p][q] = v; H[q][p] = v; }
            for (int p = 0; p < 6; p++) g[p] = sH[bb][21 + p];

            for (int i = 0; i < 6; i++) H[i][i] += sl;

            if (iter_idx[0] >= 2) {
                for (int p = 3; p < 6; p++) g[p] = 0.0f;
                for (int p = 3; p < 6; p++)
                    for (int q = 3; q < 6; q++) H[p][q] += 1.0e8f;
            }
            for (int i = 0; i < 6; i++) H[i][i] += 1.0f;
            for (int i = 0; i < 6; i++) H[i][i] += 0.01f * H[i][i];

            double A[6][7];
            for (int i = 0; i < 6; i++) {
                for (int j = 0; j < 6; j++) A[i][j] = (double)H[i][j];
                A[i][6] = (double)g[i];
            }
            for (int c = 0; c < 6; c++) {
                int piv = c; double mx = fabs(A[c][c]);
                for (int rr = c + 1; rr < 6; rr++) {
                    double a = fabs(A[rr][c]);
                    if (a > mx) { mx = a; piv = rr; }
                }
                if (piv != c) {
                    for (int j = c; j < 7; j++) {
                        double tmp = A[c][j]; A[c][j] = A[piv][j]; A[piv][j] = tmp;
                    }
                }
                double dinv = 1.0 / A[c][c];
                for (int rr = c + 1; rr < 6; rr++) {
                    double f = A[rr][c] * dinv;
                    for (int j = c; j < 7; j++) A[rr][j] -= f * A[c][j];
                }
            }
            double x[6];
            for (int i = 5; i >= 0; i--) {
                double s = A[i][6];
                for (int j = i + 1; j < 6; j++) s -= A[i][j] * x[j];
                x[i] = s / A[i][i];
            }

            bool anynan = false;
            float pose[6];
            for (int p = 0; p < 6; p++) {
                pose[p] = (float)x[p];
                g_pose[bb * 6 + p] = pose[p];
                if (isnan(pose[p])) anynan = true;
            }
            if (anynan) atomicOr(&s_nan, 1);
            for (int p = 0; p < 6; p++) sH[bb][p] = pose[p];
        }
        __syncthreads();

        if (t == 0) g_nanflag = s_nan;
        if (bb < B) {
            for (int p = 0; p < 6; p++) {
                float v = fminf(fmaxf(sH[bb][p], -2.0f), 2.0f);
                out[bb * 6 + p] = s_nan ? 0.0f : v;
            }
        }
        __threadfence();
        __syncthreads();
        if (t == 0) atomicAdd(&g_epoch, 1u);   // release: pose published
    }

    // ---- phase 3: wait for pose, then depth on our own (b, range) ---------
    if (threadIdx.x == 0) {
        while (*(volatile unsigned*)&g_epoch == epoch0)
            __nanosleep(64);
    }
    __syncthreads();
    __threadfence();   // acquire

    float p0 = __ldcg(&g_pose[b * 6 + 0]);
    float p1 = __ldcg(&g_pose[b * 6 + 1]);
    float p2 = __ldcg(&g_pose[b * 6 + 2]);
    float p3 = __ldcg(&g_pose[b * 6 + 3]);
    float p4 = __ldcg(&g_pose[b * 6 + 4]);
    float p5 = __ldcg(&g_pose[b * 6 + 5]);
    int nanf = __ldcg(&g_nanflag);

    float* dout = out + (size_t)B * 6 + bn0;
    for (int n = start + threadIdx.x; n < end; n += TPB) {
        size_t idx = bn0 + n;
        float4 s0 = __ldcs(&g_s0[idx]);
        float4 s1 = __ldcs(&g_s1[idx]);
        float v = s0.x * p0 + s0.y * p1 + s0.z * p2
                + s0.w * p3 + s1.x * p4 + s1.y * p5;
        float d = s1.w * (s1.z - v);
        d = fminf(fmaxf(d, -5.0f), 5.0f);
        dout[n] = nanf ? 0.0f : d;
    }
}

extern "C" void kernel_launch(void* const* d_in, const int* in_sizes, int n_in,
                              void* d_out, int out_size)
{
    const float* r      = (const float*)d_in[0];
    const float* w      = (const float*)d_in[1];
    const float* Jp     = (const float*)d_in[2];
    const float* Jd     = (const float*)d_in[3];
    const float* lmbda  = (const float*)d_in[4];
    const int*   iter_i = (const int*)d_in[5];
    float* out = (float*)d_out;

    int B = in_sizes[4];
    int N = in_sizes[0] / (2 * B);

    dim3 grid(RBLK, B);
    dba_kernel<<<grid, TPB>>>(r, w, Jp, Jd, lmbda, iter_i, out, N, B);
}